// round 15
// baseline (speedup 1.0000x reference)
#include <cuda_runtime.h>
#include <math.h>

#define LTOK   4096
#define NB     4
#define EDIM   512
#define MSLOT  12
#define DFFDIM 2048
#define NCYC   3
#define SCALE_Q 0.044194173824159216f   // 512^-0.5
#define LNEPS   1e-5f
#define NCOLB  (LTOK/128)               // 32 col-blocks in logits

// ---------------- scratch ----------------
__device__ float g_Kp[NB*LTOK*EDIM];
__device__ float g_Vp[NB*LTOK*EDIM];
__device__ float g_Vf[NB*LTOK*EDIM];
__device__ float g_VfR[NB*LTOK*EDIM];        // tf32-rounded V (for exact cp.async in PV)
__device__ float g_P[NB*LTOK*LTOK];          // tf32(exp(gated logit - M_blk))
__device__ float g_Pmax[NB*LTOK*NCOLB];
__device__ float g_Psum[NB*LTOK*NCOLB];
__device__ float g_Rmax[NB*LTOK];
__device__ float g_Rinv[NB*LTOK];
__device__ float g_slots[NB*MSLOT*EDIM];
__device__ float g_Qs[NB*MSLOT*EDIM];
__device__ float g_att[NB*MSLOT*LTOK];
__device__ float g_attsm[NB*MSLOT*LTOK];
__device__ float g_srcn[NB*MSLOT*EDIM];
__device__ float g_h[NB*MSLOT*DFFDIM];
__device__ float g_srcPart[8][NB*MSLOT*EDIM];
__device__ float g_f2[NB*MSLOT*EDIM];
// tf32-rounded operands (exactness for cp.async raw moves)
__device__ float g_qR[NB*LTOK*EDIM];
__device__ float g_kR[NB*LTOK*EDIM];
__device__ float g_vR[NB*LTOK*EDIM];
__device__ float g_QfR[NB*LTOK*EDIM];
__device__ float g_KfR[NB*LTOK*EDIM];
__device__ float g_wR[5][EDIM*EDIM];         // sWk, sWv, Wq, Wk, Wv

__device__ __forceinline__ unsigned f2tf(float f) {
    unsigned u; asm("cvt.rna.tf32.f32 %0, %1;" : "=r"(u) : "f"(f)); return u;
}
__device__ __forceinline__ float tf32r(float f) { return __uint_as_float(f2tf(f)); }

__device__ __forceinline__ void cp16(unsigned* smem_dst, const float* gptr) {
    unsigned s = (unsigned)__cvta_generic_to_shared(smem_dst);
    asm volatile("cp.async.cg.shared.global [%0], [%1], 16;\n" :: "r"(s), "l"(gptr));
}
#define CP_COMMIT() asm volatile("cp.async.commit_group;\n" ::: "memory")
#define CP_WAIT0()  asm volatile("cp.async.wait_group 0;\n" ::: "memory")
#define CP_WAIT1()  asm volatile("cp.async.wait_group 1;\n" ::: "memory")

// elementwise tf32 RNA round (float4)
__global__ void round_tf32_kernel(const float* __restrict__ in, float* __restrict__ out, int n4)
{
    int i = blockIdx.x * 256 + threadIdx.x;
    if (i < n4) {
        float4 v = ((const float4*)in)[i];
        float4 o = { tf32r(v.x), tf32r(v.y), tf32r(v.z), tf32r(v.w) };
        ((float4*)out)[i] = o;
    }
}

// ========== cp.async double-buffered tf32 MMA GEMM (NT only, inputs pre-rounded) ==========
// EPI=1: token_assign gating + stores tf32(exp(v-M_blk)) + online-softmax block partials.
// Crnd != nullptr: also store tf32-rounded copy of C.
template<int EPI>
__global__ void __launch_bounds__(256, 2)
mma_async_kernel(const float* __restrict__ A, int lda, long sAz,
                 const float* __restrict__ B, int ldb, long sBz,
                 float* __restrict__ C, int ldc, long sCz, float* __restrict__ Crnd,
                 int K, float scale,
                 const float* __restrict__ satt, const float* __restrict__ sassign,
                 float* __restrict__ pmax, float* __restrict__ psum)
{
    extern __shared__ unsigned smem[];          // 2 * (4608 + 4608) words
    int z = blockIdx.z;
    A += (long)z * sAz; B += (long)z * sBz; C += (long)z * sCz;
    int row0 = blockIdx.y * 128, col0 = blockIdx.x * 128;
    int tid = threadIdx.x, lane = tid & 31, warp = tid >> 5;
    int wm = warp >> 2, wn = warp & 3;
    int gid = lane >> 2, tig = lane & 3;
    float acc[4][4][4] = {};
    int ra = tid >> 3, ka = (tid & 7) << 2;

    {
        unsigned* As = smem; unsigned* Bs = smem + 4608;
        #pragma unroll
        for (int i = 0; i < 4; i++) {
            int r = ra + 32 * i;
            cp16(&As[r * 36 + ka], &A[(long)(row0 + r) * lda + ka]);
            cp16(&Bs[r * 36 + ka], &B[(long)(col0 + r) * ldb + ka]);
        }
        CP_COMMIT();
    }

    int nbuf = 0;
    for (int kt = 0; kt < K; kt += 32) {
        bool more = (kt + 32) < K;
        if (more) {
            unsigned* As = smem + (nbuf ^ 1) * 9216;
            unsigned* Bs = As + 4608;
            #pragma unroll
            for (int i = 0; i < 4; i++) {
                int r = ra + 32 * i;
                cp16(&As[r * 36 + ka], &A[(long)(row0 + r) * lda + kt + 32 + ka]);
                cp16(&Bs[r * 36 + ka], &B[(long)(col0 + r) * ldb + kt + 32 + ka]);
            }
            CP_COMMIT();
            CP_WAIT1();
        } else {
            CP_WAIT0();
        }
        __syncthreads();
        const unsigned* As = smem + nbuf * 9216;
        const unsigned* Bs = As + 4608;
        #pragma unroll
        for (int ks = 0; ks < 4; ks++) {
            int k0 = ks * 8;
            unsigned a[4][4], b[4][2];
            #pragma unroll
            for (int mt = 0; mt < 4; mt++) {
                int r = wm * 64 + mt * 16 + gid;
                a[mt][0] = As[r * 36 + k0 + tig];
                a[mt][1] = As[(r + 8) * 36 + k0 + tig];
                a[mt][2] = As[r * 36 + k0 + tig + 4];
                a[mt][3] = As[(r + 8) * 36 + k0 + tig + 4];
            }
            #pragma unroll
            for (int nt = 0; nt < 4; nt++) {
                int c = wn * 32 + nt * 8 + gid;
                b[nt][0] = Bs[c * 36 + k0 + tig];
                b[nt][1] = Bs[c * 36 + k0 + tig + 4];
            }
            #pragma unroll
            for (int mt = 0; mt < 4; mt++)
                #pragma unroll
                for (int nt = 0; nt < 4; nt++)
                    asm volatile(
                        "mma.sync.aligned.m16n8k8.row.col.f32.tf32.tf32.f32 "
                        "{%0,%1,%2,%3}, {%4,%5,%6,%7}, {%8,%9}, {%0,%1,%2,%3};\n"
                        : "+f"(acc[mt][nt][0]), "+f"(acc[mt][nt][1]),
                          "+f"(acc[mt][nt][2]), "+f"(acc[mt][nt][3])
                        : "r"(a[mt][0]), "r"(a[mt][1]), "r"(a[mt][2]), "r"(a[mt][3]),
                          "r"(b[nt][0]), "r"(b[nt][1]));
        }
        __syncthreads();
        nbuf ^= 1;
    }

    // ---------------- epilogue ----------------
    float* Ssa = (float*)smem;            // 128x12
    float* Ssg = (float*)smem + 1536;     // 12x128
    if (EPI) {
        const float* sa = satt + ((long)z * LTOK + row0) * MSLOT;
        #pragma unroll
        for (int i = 0; i < 6; i++) Ssa[tid + i * 256] = sa[tid + i * 256];
        #pragma unroll
        for (int i = 0; i < 6; i++) {
            int idx = tid + i * 256;
            Ssg[idx] = sassign[((long)z * MSLOT + (idx >> 7)) * LTOK + col0 + (idx & 127)];
        }
        __syncthreads();
        #pragma unroll
        for (int mt = 0; mt < 4; mt++) {
            int r0l = wm * 64 + mt * 16 + gid, r1l = r0l + 8;
            #pragma unroll
            for (int nt = 0; nt < 4; nt++) {
                int c0l = wn * 32 + nt * 8 + 2 * tig;
                float t00 = 0.f, t01 = 0.f, t10 = 0.f, t11 = 0.f;
                #pragma unroll
                for (int m = 0; m < MSLOT; m++) {
                    float sa0 = Ssa[r0l * MSLOT + m], sa1 = Ssa[r1l * MSLOT + m];
                    float sg0 = Ssg[m * 128 + c0l],   sg1 = Ssg[m * 128 + c0l + 1];
                    t00 += sa0 * sg0; t01 += sa0 * sg1;
                    t10 += sa1 * sg0; t11 += sa1 * sg1;
                }
                acc[mt][nt][0] *= t00; acc[mt][nt][1] *= t01;
                acc[mt][nt][2] *= t10; acc[mt][nt][3] *= t11;
            }
        }
    } else {
        // plain store (projection path)
        #pragma unroll
        for (int mt = 0; mt < 4; mt++) {
            int r0l = wm * 64 + mt * 16 + gid, r1l = r0l + 8;
            #pragma unroll
            for (int nt = 0; nt < 4; nt++) {
                int c0l = wn * 32 + nt * 8 + 2 * tig;
                float2 o0 = { acc[mt][nt][0] * scale, acc[mt][nt][1] * scale };
                float2 o1 = { acc[mt][nt][2] * scale, acc[mt][nt][3] * scale };
                *(float2*)&C[(long)(row0 + r0l) * ldc + col0 + c0l] = o0;
                *(float2*)&C[(long)(row0 + r1l) * ldc + col0 + c0l] = o1;
                if (Crnd) {
                    float2 q0 = { tf32r(o0.x), tf32r(o0.y) };
                    float2 q1 = { tf32r(o1.x), tf32r(o1.y) };
                    *(float2*)&Crnd[(long)z * sCz + (long)(row0 + r0l) * ldc + col0 + c0l] = q0;
                    *(float2*)&Crnd[(long)z * sCz + (long)(row0 + r1l) * ldc + col0 + c0l] = q1;
                }
            }
        }
    }
    if (EPI) {
        float* rmaxS = (float*)smem + 4608;   // [128][4]
        float* rsumS = rmaxS + 512;
        #pragma unroll
        for (int mt = 0; mt < 4; mt++)
            #pragma unroll
            for (int h = 0; h < 2; h++) {
                float mx = -3.4e38f;
                #pragma unroll
                for (int nt = 0; nt < 4; nt++) {
                    mx = fmaxf(mx, acc[mt][nt][2 * h]);
                    mx = fmaxf(mx, acc[mt][nt][2 * h + 1]);
                }
                mx = fmaxf(mx, __shfl_xor_sync(0xffffffffu, mx, 1));
                mx = fmaxf(mx, __shfl_xor_sync(0xffffffffu, mx, 2));
                if (tig == 0) rmaxS[(wm * 64 + mt * 16 + h * 8 + gid) * 4 + wn] = mx;
            }
        __syncthreads();
        #pragma unroll
        for (int mt = 0; mt < 4; mt++)
            #pragma unroll
            for (int h = 0; h < 2; h++) {
                int r = wm * 64 + mt * 16 + h * 8 + gid;
                float M = fmaxf(fmaxf(rmaxS[r * 4], rmaxS[r * 4 + 1]),
                                fmaxf(rmaxS[r * 4 + 2], rmaxS[r * 4 + 3]));
                float s = 0.f;
                #pragma unroll
                for (int nt = 0; nt < 4; nt++) {
                    float e0 = __expf(acc[mt][nt][2 * h] - M);
                    float e1 = __expf(acc[mt][nt][2 * h + 1] - M);
                    s += e0 + e1;
                    int c0l = wn * 32 + nt * 8 + 2 * tig;
                    float2 o = { tf32r(e0), tf32r(e1) };
                    *(float2*)&C[(long)(row0 + r) * ldc + col0 + c0l] = o;
                }
                s += __shfl_xor_sync(0xffffffffu, s, 1);
                s += __shfl_xor_sync(0xffffffffu, s, 2);
                if (tig == 0) rsumS[r * 4 + wn] = s;
            }
        __syncthreads();
        if (tid < 128) {
            int r = tid;
            float M = fmaxf(fmaxf(rmaxS[r * 4], rmaxS[r * 4 + 1]),
                            fmaxf(rmaxS[r * 4 + 2], rmaxS[r * 4 + 3]));
            float S = rsumS[r * 4] + rsumS[r * 4 + 1] + rsumS[r * 4 + 2] + rsumS[r * 4 + 3];
            long base = ((long)z * LTOK + row0 + r) * NCOLB + blockIdx.x;
            pmax[base] = M; psum[base] = S;
        }
    }
}

// ========== flash PV: fully cp.async NN GEMM with accumulator unit-rescaling ==========
__global__ void __launch_bounds__(256, 2)
mma_pv_flash(const float* __restrict__ P, const float* __restrict__ V,
             float* __restrict__ C,
             const float* __restrict__ rowmax, const float* __restrict__ rowinv,
             const float* __restrict__ pmax)
{
    extern __shared__ unsigned smem[];          // 2 * (A 4608 + B 4352) = 17920 words
    int z = blockIdx.z;
    const float* A = P + (long)z * LTOK * LTOK;
    const float* B = V + (long)z * EDIM;
    float* Cz = C + (long)z * EDIM;
    const int lda = LTOK, ldb = NB * EDIM, ldc = NB * EDIM;
    int row0 = blockIdx.y * 128, col0 = blockIdx.x * 128;
    int tid = threadIdx.x, lane = tid & 31, warp = tid >> 5;
    int wm = warp >> 2, wn = warp & 3;
    int gid = lane >> 2, tig = lane & 3;
    float acc[4][4][4] = {};
    int ra = tid >> 3, ka = (tid & 7) << 2;
    int kb = tid >> 5, nb = (tid & 31) << 2;

    long rowbase = (long)z * LTOK + row0;
    float curm[8];
    #pragma unroll
    for (int mt = 0; mt < 4; mt++)
        #pragma unroll
        for (int h = 0; h < 2; h++)
            curm[mt * 2 + h] = pmax[(rowbase + wm * 64 + mt * 16 + h * 8 + gid) * NCOLB];

    {
        unsigned* As = smem; unsigned* Bs = smem + 4608;
        #pragma unroll
        for (int i = 0; i < 4; i++) {
            int r = ra + 32 * i;
            cp16(&As[r * 36 + ka], &A[(long)(row0 + r) * lda + ka]);
            int k = kb + 8 * i;
            cp16(&Bs[k * 136 + nb], &B[(long)k * ldb + col0 + nb]);
        }
        CP_COMMIT();
    }

    int nbuf = 0;
    for (int kt = 0; kt < LTOK; kt += 32) {
        bool more = (kt + 32) < LTOK;
        if (more) {
            unsigned* As = smem + (nbuf ^ 1) * 8960;
            unsigned* Bs = As + 4608;
            #pragma unroll
            for (int i = 0; i < 4; i++) {
                int r = ra + 32 * i;
                cp16(&As[r * 36 + ka], &A[(long)(row0 + r) * lda + kt + 32 + ka]);
                int k = kb + 8 * i;
                cp16(&Bs[k * 136 + nb], &B[(long)(kt + 32 + k) * ldb + col0 + nb]);
            }
            CP_COMMIT();
            CP_WAIT1();
        } else {
            CP_WAIT0();
        }
        __syncthreads();

        if (kt > 0 && (kt & 127) == 0) {
            int blk = kt >> 7;
            #pragma unroll
            for (int mt = 0; mt < 4; mt++)
                #pragma unroll
                for (int h = 0; h < 2; h++) {
                    long rr = rowbase + wm * 64 + mt * 16 + h * 8 + gid;
                    float nm = pmax[rr * NCOLB + blk];
                    float ratio = __expf(curm[mt * 2 + h] - nm);
                    curm[mt * 2 + h] = nm;
                    #pragma unroll
                    for (int nt = 0; nt < 4; nt++) {
                        acc[mt][nt][2 * h]     *= ratio;
                        acc[mt][nt][2 * h + 1] *= ratio;
                    }
                }
        }

        const unsigned* As = smem + nbuf * 8960;
        const unsigned* Bs = As + 4608;
        #pragma unroll
        for (int ks = 0; ks < 4; ks++) {
            int k0 = ks * 8;
            unsigned a[4][4], b[4][2];
            #pragma unroll
            for (int mt = 0; mt < 4; mt++) {
                int r = wm * 64 + mt * 16 + gid;
                a[mt][0] = As[r * 36 + k0 + tig];
                a[mt][1] = As[(r + 8) * 36 + k0 + tig];
                a[mt][2] = As[r * 36 + k0 + tig + 4];
                a[mt][3] = As[(r + 8) * 36 + k0 + tig + 4];
            }
            #pragma unroll
            for (int nt = 0; nt < 4; nt++) {
                int c = wn * 32 + nt * 8 + gid;
                b[nt][0] = Bs[(k0 + tig) * 136 + c];
                b[nt][1] = Bs[(k0 + tig + 4) * 136 + c];
            }
            #pragma unroll
            for (int mt = 0; mt < 4; mt++)
                #pragma unroll
                for (int nt = 0; nt < 4; nt++)
                    asm volatile(
                        "mma.sync.aligned.m16n8k8.row.col.f32.tf32.tf32.f32 "
                        "{%0,%1,%2,%3}, {%4,%5,%6,%7}, {%8,%9}, {%0,%1,%2,%3};\n"
                        : "+f"(acc[mt][nt][0]), "+f"(acc[mt][nt][1]),
                          "+f"(acc[mt][nt][2]), "+f"(acc[mt][nt][3])
                        : "r"(a[mt][0]), "r"(a[mt][1]), "r"(a[mt][2]), "r"(a[mt][3]),
                          "r"(b[nt][0]), "r"(b[nt][1]));
        }
        __syncthreads();
        nbuf ^= 1;
    }

    #pragma unroll
    for (int mt = 0; mt < 4; mt++) {
        int r0l = wm * 64 + mt * 16 + gid, r1l = r0l + 8;
        long rr0 = rowbase + r0l, rr1 = rowbase + r1l;
        float fa = __expf(curm[mt * 2 + 0] - rowmax[rr0]) * rowinv[rr0];
        float fb = __expf(curm[mt * 2 + 1] - rowmax[rr1]) * rowinv[rr1];
        #pragma unroll
        for (int nt = 0; nt < 4; nt++) {
            int c0l = wn * 32 + nt * 8 + 2 * tig;
            float2 o0 = { acc[mt][nt][0] * fa, acc[mt][nt][1] * fa };
            float2 o1 = { acc[mt][nt][2] * fb, acc[mt][nt][3] * fb };
            *(float2*)&Cz[(long)(row0 + r0l) * ldc + col0 + c0l] = o0;
            *(float2*)&Cz[(long)(row0 + r1l) * ldc + col0 + c0l] = o1;
        }
    }
}

// merge 32 block-partials per row -> rowmax, 1/rowsum
__global__ void stats_finish_kernel(const float* __restrict__ pmax, const float* __restrict__ psum,
                                    float* __restrict__ rmax, float* __restrict__ rinv)
{
    int row = blockIdx.x * 4 + (threadIdx.x >> 5);
    int lane = threadIdx.x & 31;
    float M = pmax[(long)row * NCOLB + lane];
    float S = psum[(long)row * NCOLB + lane];
    #pragma unroll
    for (int o = 16; o; o >>= 1) {
        float M2 = __shfl_xor_sync(0xffffffffu, M, o);
        float S2 = __shfl_xor_sync(0xffffffffu, S, o);
        float Mn = fmaxf(M, M2);
        S = S * __expf(M - Mn) + S2 * __expf(M2 - Mn);
        M = Mn;
    }
    if (lane == 0) { rmax[row] = M; rinv[row] = 1.f / S; }
}

// ---------------- small row-GEMM: 4 independent accumulators ----------------
__global__ void small_gemm_kernel(const float* __restrict__ X, int K,
                                  const float* __restrict__ W,
                                  const float* __restrict__ bias,
                                  float* __restrict__ Out, int ldo,
                                  int mode, float scale)
{
    __shared__ float xs[DFFDIM];
    int r = blockIdx.x, tid = threadIdx.x;
    for (int i = tid; i < K; i += 128) xs[i] = X[(long)r * K + i];
    __syncthreads();
    int o = blockIdx.y * 128 + tid;
    const float4* w4 = (const float4*)(W + (long)o * K);
    const float4* x4 = (const float4*)xs;
    float a0 = 0.f, a1 = 0.f, a2 = 0.f, a3 = 0.f;
    int K4 = K >> 2;
    for (int k = 0; k < K4; k += 4) {
        float4 w0 = w4[k],     x0 = x4[k];
        float4 w1 = w4[k + 1], x1 = x4[k + 1];
        float4 w2 = w4[k + 2], x2 = x4[k + 2];
        float4 w3 = w4[k + 3], x3 = x4[k + 3];
        a0 += w0.x * x0.x + w0.y * x0.y + w0.z * x0.z + w0.w * x0.w;
        a1 += w1.x * x1.x + w1.y * x1.y + w1.z * x1.z + w1.w * x1.w;
        a2 += w2.x * x2.x + w2.y * x2.y + w2.z * x2.z + w2.w * x2.w;
        a3 += w3.x * x3.x + w3.y * x3.y + w3.z * x3.z + w3.w * x3.w;
    }
    float acc = (a0 + a1) + (a2 + a3);
    float v;
    if (mode == 0) v = acc * scale;
    else if (mode == 1) { float t = acc + bias[o]; v = 0.5f * t * (1.0f + erff(t * 0.70710678118654752f)); }
    else v = acc + bias[o];
    Out[(long)r * ldo + o] = v;
}

// ---------------- softmax rows of 4096 (slot attsm only) ----------------
__global__ void softmax_rows_kernel(const float* __restrict__ In, float* __restrict__ Out)
{
    __shared__ float buf[LTOK];
    __shared__ float red[256];
    long base = (long)blockIdx.x * LTOK;
    int tid = threadIdx.x;
    float mx = -3.4e38f;
    for (int i = tid; i < LTOK; i += 256) { float v = In[base + i]; buf[i] = v; mx = fmaxf(mx, v); }
    red[tid] = mx; __syncthreads();
    for (int st = 128; st > 0; st >>= 1) { if (tid < st) red[tid] = fmaxf(red[tid], red[tid + st]); __syncthreads(); }
    mx = red[0]; __syncthreads();
    float s = 0.f;
    for (int i = tid; i < LTOK; i += 256) { float e = expf(buf[i] - mx); buf[i] = e; s += e; }
    red[tid] = s; __syncthreads();
    for (int st = 128; st > 0; st >>= 1) { if (tid < st) red[tid] += red[tid + st]; __syncthreads(); }
    float inv = 1.f / red[0];
    for (int i = tid; i < LTOK; i += 256) Out[base + i] = buf[i] * inv;
}

// ---------------- slot-phase small kernels ----------------
__global__ void init_slots_kernel(const float* __restrict__ sv)
{
    int idx = blockIdx.x * 256 + threadIdx.x;
    if (idx < NB * MSLOT * EDIM) {
        int e = idx % EDIM; int nm = idx / EDIM; int m = nm % MSLOT; int n = nm / MSLOT;
        g_slots[idx] = sv[(m * NB + n) * EDIM + e];
    }
}

__global__ void slots_out_kernel(float* __restrict__ out)
{
    int idx = blockIdx.x * 256 + threadIdx.x;
    if (idx < NB * MSLOT * EDIM) {
        int e = idx % EDIM; int nm = idx / EDIM; int m = nm % MSLOT; int n = nm / MSLOT;
        out[(m * NB + n) * EDIM + e] = g_slots[idx];
    }
}

__global__ void slot_att_kernel()
{
    int n = blockIdx.x;
    int l = blockIdx.y * 128 + threadIdx.x;
    __shared__ float Qsm[MSLOT * EDIM];
    const float* src = g_Qs + n * MSLOT * EDIM;
    for (int i = threadIdx.x; i < MSLOT * EDIM; i += 128) Qsm[i] = src[i];
    __syncthreads();
    const float4* kr = (const float4*)(g_Kp + (long)(l * NB + n) * EDIM);
    float acc[MSLOT] = {};
    for (int e4 = 0; e4 < EDIM / 4; e4++) {
        float4 kv = kr[e4];
        #pragma unroll
        for (int m = 0; m < MSLOT; m++) {
            float4 q = *(const float4*)&Qsm[m * EDIM + e4 * 4];
            acc[m] += q.x * kv.x + q.y * kv.y + q.z * kv.z + q.w * kv.w;
        }
    }
    #pragma unroll
    for (int m = 0; m < MSLOT; m++) g_att[(long)(n * MSLOT + m) * LTOK + l] = acc[m];
}

__global__ void slot_assign_kernel(float* __restrict__ outp)
{
    int n = blockIdx.x;
    int l = blockIdx.y * 256 + threadIdx.x;
    float v[MSLOT]; float mx = -3.4e38f;
    #pragma unroll
    for (int m = 0; m < MSLOT; m++) { v[m] = g_att[(long)(n * MSLOT + m) * LTOK + l]; mx = fmaxf(mx, v[m]); }
    float s = 0.f;
    #pragma unroll
    for (int m = 0; m < MSLOT; m++) { v[m] = expf(v[m] - mx); s += v[m]; }
    float inv = 1.f / s;
    #pragma unroll
    for (int m = 0; m < MSLOT; m++) outp[(long)(n * MSLOT + m) * LTOK + l] = v[m] * inv;
}

__global__ void slot_update_kernel()
{
    int n = blockIdx.x;
    int e = blockIdx.y * 128 + threadIdx.x;
    int z = blockIdx.z;
    __shared__ float w[MSLOT][128];
    float acc[MSLOT] = {};
    for (int l0 = z * 512; l0 < z * 512 + 512; l0 += 128) {
        #pragma unroll
        for (int m = 0; m < MSLOT; m++)
            w[m][threadIdx.x] = g_attsm[(long)(n * MSLOT + m) * LTOK + l0 + threadIdx.x];
        __syncthreads();
        for (int lt = 0; lt < 128; lt++) {
            float v = g_Vp[(long)((l0 + lt) * NB + n) * EDIM + e];
            #pragma unroll
            for (int m = 0; m < MSLOT; m++) acc[m] += w[m][lt] * v;
        }
        __syncthreads();
    }
    #pragma unroll
    for (int m = 0; m < MSLOT; m++)
        g_srcPart[z][(n * MSLOT + m) * EDIM + e] = acc[m];
}

__global__ void ln1_kernel(const float* __restrict__ gg, const float* __restrict__ bb)
{
    int r = blockIdx.x, tid = threadIdx.x;
    __shared__ float xs[EDIM];
    __shared__ float red[256];
    for (int i = tid; i < EDIM; i += 256) {
        float v = g_slots[r * EDIM + i];
        #pragma unroll
        for (int zz = 0; zz < 8; zz++) v += g_srcPart[zz][r * EDIM + i];
        xs[i] = v;
    }
    __syncthreads();
    float s = 0.f;
    for (int i = tid; i < EDIM; i += 256) s += xs[i];
    red[tid] = s; __syncthreads();
    for (int st = 128; st > 0; st >>= 1) { if (tid < st) red[tid] += red[tid + st]; __syncthreads(); }
    float mean = red[0] / EDIM;
    __syncthreads();
    float sq = 0.f;
    for (int i = tid; i < EDIM; i += 256) { float d = xs[i] - mean; sq += d * d; }
    red[tid] = sq; __syncthreads();
    for (int st = 128; st > 0; st >>= 1) { if (tid < st) red[tid] += red[tid + st]; __syncthreads(); }
    float rstd = rsqrtf(red[0] / EDIM + LNEPS);
    for (int i = tid; i < EDIM; i += 256)
        g_srcn[r * EDIM + i] = (xs[i] - mean) * rstd * gg[i] + bb[i];
}

__global__ void ln2_kernel(const float* __restrict__ gg, const float* __restrict__ bb)
{
    int r = blockIdx.x, tid = threadIdx.x;
    __shared__ float xs[EDIM];
    __shared__ float red[256];
    for (int i = tid; i < EDIM; i += 256)
        xs[i] = g_srcn[r * EDIM + i] + g_f2[r * EDIM + i];
    __syncthreads();
    float s = 0.f;
    for (int i = tid; i < EDIM; i += 256) s += xs[i];
    red[tid] = s; __syncthreads();
    for (int st = 128; st > 0; st >>= 1) { if (tid < st) red[tid] += red[tid + st]; __syncthreads(); }
    float mean = red[0] / EDIM;
    __syncthreads();
    float sq = 0.f;
    for (int i = tid; i < EDIM; i += 256) { float d = xs[i] - mean; sq += d * d; }
    red[tid] = sq; __syncthreads();
    for (int st = 128; st > 0; st >>= 1) { if (tid < st) red[tid] += red[tid + st]; __syncthreads(); }
    float rstd = rsqrtf(red[0] / EDIM + LNEPS);
    for (int i = tid; i < EDIM; i += 256)
        g_slots[r * EDIM + i] = (xs[i] - mean) * rstd * gg[i] + bb[i];
}

__global__ void slot_att_final_kernel(const float* __restrict__ Qf, float* __restrict__ outp)
{
    int n = blockIdx.x;
    int l = blockIdx.y * 128 + threadIdx.x;
    __shared__ float S[MSLOT * EDIM];
    const float* sp = g_slots + n * MSLOT * EDIM;
    for (int i = threadIdx.x; i < MSLOT * EDIM; i += 128) S[i] = sp[i];
    __syncthreads();
    const float4* q4 = (const float4*)(Qf + (long)(l * NB + n) * EDIM);
    float acc[MSLOT] = {};
    for (int e4 = 0; e4 < EDIM / 4; e4++) {
        float4 q = q4[e4];
        #pragma unroll
        for (int m = 0; m < MSLOT; m++) {
            float4 sv = *(const float4*)&S[m * EDIM + e4 * 4];
            acc[m] += sv.x * q.x + sv.y * q.y + sv.z * q.z + sv.w * q.w;
        }
    }
    float mx = -3.4e38f;
    #pragma unroll
    for (int m = 0; m < MSLOT; m++) mx = fmaxf(mx, acc[m]);
    float s = 0.f;
    #pragma unroll
    for (int m = 0; m < MSLOT; m++) { acc[m] = expf(acc[m] - mx); s += acc[m]; }
    float inv = 1.f / s;
    #pragma unroll
    for (int m = 0; m < MSLOT; m++) outp[(long)(n * LTOK + l) * MSLOT + m] = acc[m] * inv;
}

// ---------------- host launcher ----------------
extern "C" void kernel_launch(void* const* d_in, const int* in_sizes, int n_in,
                              void* d_out, int out_size)
{
    const float* queries = (const float*)d_in[0];
    const float* keys    = (const float*)d_in[1];
    const float* values  = (const float*)d_in[2];
    const float* slot_v  = (const float*)d_in[3];
    const float* sWq = (const float*)d_in[4];
    const float* sWk = (const float*)d_in[5];
    const float* sWv = (const float*)d_in[6];
    const float* Wq  = (const float*)d_in[7];
    const float* Wk  = (const float*)d_in[8];
    const float* Wv  = (const float*)d_in[9];
    const float* l1_w = (const float*)d_in[10];
    const float* l1_b = (const float*)d_in[11];
    const float* l2_w = (const float*)d_in[12];
    const float* l2_b = (const float*)d_in[13];
    const float* n1_g = (const float*)d_in[14];
    const float* n1_b = (const float*)d_in[15];
    const float* n2_g = (const float*)d_in[16];
    const float* n2_b = (const float*)d_in[17];
    float* out = (float*)d_out;

    float *Kp, *Vp, *Vf, *VfR, *P, *Pmax, *Psum, *Rmax, *Rinv;
    float *slots, *Qs, *att, *attsm, *srcn, *hbuf, *f2;
    float *qR, *kR, *vR, *QfR, *KfR, *wR;
    cudaGetSymbolAddress((void**)&Kp,    g_Kp);
    cudaGetSymbolAddress((void**)&Vp,    g_Vp);
    cudaGetSymbolAddress((void**)&Vf,    g_Vf);
    cudaGetSymbolAddress((void**)&VfR,   g_VfR);
    cudaGetSymbolAddress((void**)&P,     g_P);
    cudaGetSymbolAddress((void**)&Pmax,  g_Pmax);
    cudaGetSymbolAddress((void**)&Psum,  g_Psum);
    cudaGetSymbolAddress((void**)&Rmax,  g_Rmax);
    cudaGetSymbolAddress((void**)&Rinv,  g_Rinv);
    cudaGetSymbolAddress((void**)&slots, g_slots);
    cudaGetSymbolAddress((void**)&Qs,    g_Qs);
    cudaGetSymbolAddress((void**)&att,   g_att);
    cudaGetSymbolAddress((void**)&attsm, g_attsm);
    cudaGetSymbolAddress((void**)&srcn,  g_srcn);
    cudaGetSymbolAddress((void**)&hbuf,  g_h);
    cudaGetSymbolAddress((void**)&f2,    g_f2);
    cudaGetSymbolAddress((void**)&qR,    g_qR);
    cudaGetSymbolAddress((void**)&kR,    g_kR);
    cudaGetSymbolAddress((void**)&vR,    g_vR);
    cudaGetSymbolAddress((void**)&QfR,   g_QfR);
    cudaGetSymbolAddress((void**)&KfR,   g_KfR);
    cudaGetSymbolAddress((void**)&wR,    g_wR);

    const int o_Q       = LTOK * NB * EDIM;
    const int o_K       = 2 * o_Q;
    const int o_slots   = 3 * o_Q;
    const int o_sassign = o_slots + MSLOT * NB * EDIM;
    const int o_satt    = o_sassign + NB * MSLOT * LTOK;

    const int SMEM_ASYNC = 2 * (4608 + 4608) * 4;   // 73728 B
    const int SMEM_PV    = 2 * (4608 + 4352) * 4;   // 71680 B
    cudaFuncSetAttribute(mma_async_kernel<0>, cudaFuncAttributeMaxDynamicSharedMemorySize, SMEM_ASYNC);
    cudaFuncSetAttribute(mma_async_kernel<1>, cudaFuncAttributeMaxDynamicSharedMemorySize, SMEM_ASYNC);
    cudaFuncSetAttribute(mma_pv_flash,        cudaFuncAttributeMaxDynamicSharedMemorySize, SMEM_PV);

    // ---- fork/join resources (created fresh each call; capture-legal immediate ops) ----
    cudaStream_t s2;
    cudaEvent_t eFork, eJoin;
    cudaStreamCreateWithFlags(&s2, cudaStreamNonBlocking);
    cudaEventCreateWithFlags(&eFork, cudaEventDisableTiming);
    cudaEventCreateWithFlags(&eJoin, cudaEventDisableTiming);

    // ---- pre-round operands to tf32 (makes cp.async raw moves exact) ----
    const int NTOK4 = (NB * LTOK * EDIM) / 4;       // 2097152
    const int NW4   = (EDIM * EDIM) / 4;            // 65536
    round_tf32_kernel<<<(NTOK4 + 255) / 256, 256>>>(queries, qR, NTOK4);
    round_tf32_kernel<<<(NTOK4 + 255) / 256, 256>>>(keys,    kR, NTOK4);
    round_tf32_kernel<<<(NTOK4 + 255) / 256, 256>>>(values,  vR, NTOK4);
    round_tf32_kernel<<<(NW4 + 255) / 256, 256>>>(sWk, wR + 0L * EDIM * EDIM, NW4);
    round_tf32_kernel<<<(NW4 + 255) / 256, 256>>>(sWv, wR + 1L * EDIM * EDIM, NW4);
    round_tf32_kernel<<<(NW4 + 255) / 256, 256>>>(Wq,  wR + 2L * EDIM * EDIM, NW4);
    round_tf32_kernel<<<(NW4 + 255) / 256, 256>>>(Wk,  wR + 3L * EDIM * EDIM, NW4);
    round_tf32_kernel<<<(NW4 + 255) / 256, 256>>>(Wv,  wR + 4L * EDIM * EDIM, NW4);

    // ---- fork: side stream runs final Q/K/V projections concurrently with slot phase ----
    cudaEventRecord(eFork, 0);
    cudaStreamWaitEvent(s2, eFork, 0);

    dim3 gProj(EDIM / 128, (LTOK * NB) / 128, 1);

    mma_async_kernel<0><<<gProj, 256, SMEM_ASYNC, s2>>>(qR, EDIM, 0, wR + 2L * EDIM * EDIM, EDIM, 0,
                                                        out + o_Q, EDIM, 0, QfR, EDIM, SCALE_Q, 0, 0, 0, 0);
    mma_async_kernel<0><<<gProj, 256, SMEM_ASYNC, s2>>>(kR, EDIM, 0, wR + 3L * EDIM * EDIM, EDIM, 0,
                                                        out + o_K, EDIM, 0, KfR, EDIM, 1.0f, 0, 0, 0, 0);
    mma_async_kernel<0><<<gProj, 256, SMEM_ASYNC, s2>>>(vR, EDIM, 0, wR + 4L * EDIM * EDIM, EDIM, 0,
                                                        Vf, EDIM, 0, VfR, EDIM, 1.0f, 0, 0, 0, 0);
    cudaEventRecord(eJoin, s2);

    // ---- main stream: slot-phase pipeline ----
    mma_async_kernel<0><<<gProj, 256, SMEM_ASYNC>>>(qR, EDIM, 0, wR + 0L * EDIM * EDIM, EDIM, 0,
                                                    Kp, EDIM, 0, 0, EDIM, 1.0f, 0, 0, 0, 0);
    mma_async_kernel<0><<<gProj, 256, SMEM_ASYNC>>>(qR, EDIM, 0, wR + 1L * EDIM * EDIM, EDIM, 0,
                                                    Vp, EDIM, 0, 0, EDIM, 1.0f, 0, 0, 0, 0);
    init_slots_kernel<<<96, 256>>>(slot_v);

    for (int c = 0; c < NCYC; c++) {
        small_gemm_kernel<<<dim3(NB * MSLOT, EDIM / 128), 128>>>(slots, EDIM, sWq, 0, Qs, EDIM, 0, SCALE_Q);
        slot_att_kernel<<<dim3(NB, LTOK / 128), 128>>>();
        softmax_rows_kernel<<<NB * MSLOT, 256>>>(att, attsm);
        if (c == NCYC - 1)
            slot_assign_kernel<<<dim3(NB, LTOK / 256), 256>>>(out + o_sassign);
        slot_update_kernel<<<dim3(NB, EDIM / 128, 8), 128>>>();
        ln1_kernel<<<NB * MSLOT, 256>>>(n1_g, n1_b);
        small_gemm_kernel<<<dim3(NB * MSLOT, DFFDIM / 128), 128>>>(srcn, EDIM, l1_w, l1_b, hbuf, DFFDIM, 1, 1.0f);
        small_gemm_kernel<<<dim3(NB * MSLOT, EDIM / 128), 128>>>(hbuf, DFFDIM, l2_w, l2_b, f2, EDIM, 2, 1.0f);
        ln2_kernel<<<NB * MSLOT, 256>>>(n2_g, n2_b);
    }

    slots_out_kernel<<<96, 256>>>(out + o_slots);

    // ---- join: attention tail needs Qf/Kf/VfR from the side stream ----
    cudaStreamWaitEvent(0, eJoin, 0);

    slot_att_final_kernel<<<dim3(NB, LTOK / 128), 128>>>(out + o_Q, out + o_satt);

    // logits (gated) -> exp'd P + online-softmax block partials
    mma_async_kernel<1><<<dim3(NCOLB, LTOK / 128, NB), 256, SMEM_ASYNC>>>(
        QfR, NB * EDIM, EDIM,
        KfR, NB * EDIM, EDIM,
        P, LTOK, (long)LTOK * LTOK, 0,
        EDIM, 1.0f, out + o_satt, out + o_sassign, Pmax, Psum);
    stats_finish_kernel<<<NB * LTOK / 4, 128>>>(Pmax, Psum, Rmax, Rinv);
    // out = softmax(P) @ V  (flash-style, fully cp.async)
    mma_pv_flash<<<dim3(EDIM / 128, LTOK / 128, NB), 256, SMEM_PV>>>(
        P, VfR, out, Rmax, Rinv, Pmax);
}

// round 16
// speedup vs baseline: 1.0210x; 1.0210x over previous
#include <cuda_runtime.h>
#include <math.h>

#define LTOK   4096
#define NB     4
#define EDIM   512
#define MSLOT  12
#define DFFDIM 2048
#define NCYC   3
#define SCALE_Q 0.044194173824159216f   // 512^-0.5
#define LNEPS   1e-5f
#define NCOLB  (LTOK/128)               // 32 col-blocks in logits

// ---------------- scratch ----------------
__device__ float g_Kp[NB*LTOK*EDIM];
__device__ float g_Vp[NB*LTOK*EDIM];
__device__ float g_Vf[NB*LTOK*EDIM];
__device__ float g_VfR[NB*LTOK*EDIM];        // tf32-rounded V (for exact cp.async in PV)
__device__ float g_P[NB*LTOK*LTOK];          // tf32(exp(gated logit - M_blk))
__device__ float g_Pmax[NB*LTOK*NCOLB];
__device__ float g_Psum[NB*LTOK*NCOLB];
__device__ float g_Rmax[NB*LTOK];
__device__ float g_Rinv[NB*LTOK];
__device__ float g_slots[NB*MSLOT*EDIM];
__device__ float g_Qs[NB*MSLOT*EDIM];
__device__ float g_att[NB*MSLOT*LTOK];
__device__ float g_attsm[NB*MSLOT*LTOK];
__device__ float g_srcn[NB*MSLOT*EDIM];
__device__ float g_h[NB*MSLOT*DFFDIM];
__device__ float g_srcPart[8][NB*MSLOT*EDIM];
__device__ float g_f2[NB*MSLOT*EDIM];
// tf32-rounded operands (exactness for cp.async raw moves)
__device__ float g_qR[NB*LTOK*EDIM];
__device__ float g_kR[NB*LTOK*EDIM];
__device__ float g_vR[NB*LTOK*EDIM];
__device__ float g_QfR[NB*LTOK*EDIM];
__device__ float g_KfR[NB*LTOK*EDIM];
__device__ float g_wR[5][EDIM*EDIM];         // sWk, sWv, Wq, Wk, Wv

__device__ __forceinline__ unsigned f2tf(float f) {
    unsigned u; asm("cvt.rna.tf32.f32 %0, %1;" : "=r"(u) : "f"(f)); return u;
}
__device__ __forceinline__ float tf32r(float f) { return __uint_as_float(f2tf(f)); }

__device__ __forceinline__ void cp16(unsigned* smem_dst, const float* gptr) {
    unsigned s = (unsigned)__cvta_generic_to_shared(smem_dst);
    asm volatile("cp.async.cg.shared.global [%0], [%1], 16;\n" :: "r"(s), "l"(gptr));
}
#define CP_COMMIT() asm volatile("cp.async.commit_group;\n" ::: "memory")
#define CP_WAIT0()  asm volatile("cp.async.wait_group 0;\n" ::: "memory")
#define CP_WAIT1()  asm volatile("cp.async.wait_group 1;\n" ::: "memory")

// ldmatrix fragment loads (tf32-as-2xb16 trick; mapping = mma operand layout)
__device__ __forceinline__ void ldsm_x4(unsigned& r0, unsigned& r1, unsigned& r2, unsigned& r3, unsigned addr) {
    asm volatile("ldmatrix.sync.aligned.m8n8.x4.shared.b16 {%0,%1,%2,%3}, [%4];"
        : "=r"(r0), "=r"(r1), "=r"(r2), "=r"(r3) : "r"(addr));
}
__device__ __forceinline__ void ldsm_x2(unsigned& r0, unsigned& r1, unsigned addr) {
    asm volatile("ldmatrix.sync.aligned.m8n8.x2.shared.b16 {%0,%1}, [%2];"
        : "=r"(r0), "=r"(r1) : "r"(addr));
}

// elementwise tf32 RNA round (float4)
__global__ void round_tf32_kernel(const float* __restrict__ in, float* __restrict__ out, int n4)
{
    int i = blockIdx.x * 256 + threadIdx.x;
    if (i < n4) {
        float4 v = ((const float4*)in)[i];
        float4 o = { tf32r(v.x), tf32r(v.y), tf32r(v.z), tf32r(v.w) };
        ((float4*)out)[i] = o;
    }
}

// ========== cp.async double-buffered tf32 MMA GEMM (NT only, inputs pre-rounded) ==========
// Fragment loads via ldmatrix (conflict-free at pitch 36: 36*dr mod 32 = 4*dr).
// EPI=1: token_assign gating + stores tf32(exp(v-M_blk)) + online-softmax block partials.
// Crnd != nullptr: also store tf32-rounded copy of C.
template<int EPI>
__global__ void __launch_bounds__(256, 2)
mma_async_kernel(const float* __restrict__ A, int lda, long sAz,
                 const float* __restrict__ B, int ldb, long sBz,
                 float* __restrict__ C, int ldc, long sCz, float* __restrict__ Crnd,
                 int K, float scale,
                 const float* __restrict__ satt, const float* __restrict__ sassign,
                 float* __restrict__ pmax, float* __restrict__ psum)
{
    extern __shared__ unsigned smem[];          // 2 * (4608 + 4608) words
    int z = blockIdx.z;
    A += (long)z * sAz; B += (long)z * sBz; C += (long)z * sCz;
    int row0 = blockIdx.y * 128, col0 = blockIdx.x * 128;
    int tid = threadIdx.x, lane = tid & 31, warp = tid >> 5;
    int wm = warp >> 2, wn = warp & 3;
    int gid = lane >> 2, tig = lane & 3;
    float acc[4][4][4] = {};
    int ra = tid >> 3, ka = (tid & 7) << 2;

    unsigned smem_b = (unsigned)__cvta_generic_to_shared(smem);
    // ldmatrix lane geometry
    int a_row = (lane & 7) + ((lane >> 3) & 1) * 8;   // 0..15
    int a_col = (lane >> 4) * 4;                      // 0 or 4  (tiles 2,3)
    int b_row = lane & 7;
    int b_col = ((lane >> 3) & 1) * 4;

    {
        unsigned* As = smem; unsigned* Bs = smem + 4608;
        #pragma unroll
        for (int i = 0; i < 4; i++) {
            int r = ra + 32 * i;
            cp16(&As[r * 36 + ka], &A[(long)(row0 + r) * lda + ka]);
            cp16(&Bs[r * 36 + ka], &B[(long)(col0 + r) * ldb + ka]);
        }
        CP_COMMIT();
    }

    int nbuf = 0;
    for (int kt = 0; kt < K; kt += 32) {
        bool more = (kt + 32) < K;
        if (more) {
            unsigned* As = smem + (nbuf ^ 1) * 9216;
            unsigned* Bs = As + 4608;
            #pragma unroll
            for (int i = 0; i < 4; i++) {
                int r = ra + 32 * i;
                cp16(&As[r * 36 + ka], &A[(long)(row0 + r) * lda + kt + 32 + ka]);
                cp16(&Bs[r * 36 + ka], &B[(long)(col0 + r) * ldb + kt + 32 + ka]);
            }
            CP_COMMIT();
            CP_WAIT1();
        } else {
            CP_WAIT0();
        }
        __syncthreads();
        unsigned baseA = smem_b + (nbuf * 9216) * 4;
        unsigned baseB = baseA + 4608 * 4;
        #pragma unroll
        for (int ks = 0; ks < 4; ks++) {
            int k0 = ks * 8;
            unsigned a[4][4], b[4][2];
            #pragma unroll
            for (int mt = 0; mt < 4; mt++)
                ldsm_x4(a[mt][0], a[mt][1], a[mt][2], a[mt][3],
                        baseA + ((wm * 64 + mt * 16 + a_row) * 36 + k0 + a_col) * 4);
            #pragma unroll
            for (int nt = 0; nt < 4; nt++)
                ldsm_x2(b[nt][0], b[nt][1],
                        baseB + ((wn * 32 + nt * 8 + b_row) * 36 + k0 + b_col) * 4);
            #pragma unroll
            for (int mt = 0; mt < 4; mt++)
                #pragma unroll
                for (int nt = 0; nt < 4; nt++)
                    asm volatile(
                        "mma.sync.aligned.m16n8k8.row.col.f32.tf32.tf32.f32 "
                        "{%0,%1,%2,%3}, {%4,%5,%6,%7}, {%8,%9}, {%0,%1,%2,%3};\n"
                        : "+f"(acc[mt][nt][0]), "+f"(acc[mt][nt][1]),
                          "+f"(acc[mt][nt][2]), "+f"(acc[mt][nt][3])
                        : "r"(a[mt][0]), "r"(a[mt][1]), "r"(a[mt][2]), "r"(a[mt][3]),
                          "r"(b[nt][0]), "r"(b[nt][1]));
        }
        __syncthreads();
        nbuf ^= 1;
    }

    // ---------------- epilogue ----------------
    float* Ssa = (float*)smem;            // 128x12
    float* Ssg = (float*)smem + 1536;     // 12x128
    if (EPI) {
        const float* sa = satt + ((long)z * LTOK + row0) * MSLOT;
        #pragma unroll
        for (int i = 0; i < 6; i++) Ssa[tid + i * 256] = sa[tid + i * 256];
        #pragma unroll
        for (int i = 0; i < 6; i++) {
            int idx = tid + i * 256;
            Ssg[idx] = sassign[((long)z * MSLOT + (idx >> 7)) * LTOK + col0 + (idx & 127)];
        }
        __syncthreads();
        #pragma unroll
        for (int mt = 0; mt < 4; mt++) {
            int r0l = wm * 64 + mt * 16 + gid, r1l = r0l + 8;
            #pragma unroll
            for (int nt = 0; nt < 4; nt++) {
                int c0l = wn * 32 + nt * 8 + 2 * tig;
                float t00 = 0.f, t01 = 0.f, t10 = 0.f, t11 = 0.f;
                #pragma unroll
                for (int m = 0; m < MSLOT; m++) {
                    float sa0 = Ssa[r0l * MSLOT + m], sa1 = Ssa[r1l * MSLOT + m];
                    float sg0 = Ssg[m * 128 + c0l],   sg1 = Ssg[m * 128 + c0l + 1];
                    t00 += sa0 * sg0; t01 += sa0 * sg1;
                    t10 += sa1 * sg0; t11 += sa1 * sg1;
                }
                acc[mt][nt][0] *= t00; acc[mt][nt][1] *= t01;
                acc[mt][nt][2] *= t10; acc[mt][nt][3] *= t11;
            }
        }
    } else {
        // plain store (projection path)
        #pragma unroll
        for (int mt = 0; mt < 4; mt++) {
            int r0l = wm * 64 + mt * 16 + gid, r1l = r0l + 8;
            #pragma unroll
            for (int nt = 0; nt < 4; nt++) {
                int c0l = wn * 32 + nt * 8 + 2 * tig;
                float2 o0 = { acc[mt][nt][0] * scale, acc[mt][nt][1] * scale };
                float2 o1 = { acc[mt][nt][2] * scale, acc[mt][nt][3] * scale };
                *(float2*)&C[(long)(row0 + r0l) * ldc + col0 + c0l] = o0;
                *(float2*)&C[(long)(row0 + r1l) * ldc + col0 + c0l] = o1;
                if (Crnd) {
                    float2 q0 = { tf32r(o0.x), tf32r(o0.y) };
                    float2 q1 = { tf32r(o1.x), tf32r(o1.y) };
                    *(float2*)&Crnd[(long)z * sCz + (long)(row0 + r0l) * ldc + col0 + c0l] = q0;
                    *(float2*)&Crnd[(long)z * sCz + (long)(row0 + r1l) * ldc + col0 + c0l] = q1;
                }
            }
        }
    }
    if (EPI) {
        float* rmaxS = (float*)smem + 4608;   // [128][4]
        float* rsumS = rmaxS + 512;
        #pragma unroll
        for (int mt = 0; mt < 4; mt++)
            #pragma unroll
            for (int h = 0; h < 2; h++) {
                float mx = -3.4e38f;
                #pragma unroll
                for (int nt = 0; nt < 4; nt++) {
                    mx = fmaxf(mx, acc[mt][nt][2 * h]);
                    mx = fmaxf(mx, acc[mt][nt][2 * h + 1]);
                }
                mx = fmaxf(mx, __shfl_xor_sync(0xffffffffu, mx, 1));
                mx = fmaxf(mx, __shfl_xor_sync(0xffffffffu, mx, 2));
                if (tig == 0) rmaxS[(wm * 64 + mt * 16 + h * 8 + gid) * 4 + wn] = mx;
            }
        __syncthreads();
        #pragma unroll
        for (int mt = 0; mt < 4; mt++)
            #pragma unroll
            for (int h = 0; h < 2; h++) {
                int r = wm * 64 + mt * 16 + h * 8 + gid;
                float M = fmaxf(fmaxf(rmaxS[r * 4], rmaxS[r * 4 + 1]),
                                fmaxf(rmaxS[r * 4 + 2], rmaxS[r * 4 + 3]));
                float s = 0.f;
                #pragma unroll
                for (int nt = 0; nt < 4; nt++) {
                    float e0 = __expf(acc[mt][nt][2 * h] - M);
                    float e1 = __expf(acc[mt][nt][2 * h + 1] - M);
                    s += e0 + e1;
                    int c0l = wn * 32 + nt * 8 + 2 * tig;
                    float2 o = { tf32r(e0), tf32r(e1) };
                    *(float2*)&C[(long)(row0 + r) * ldc + col0 + c0l] = o;
                }
                s += __shfl_xor_sync(0xffffffffu, s, 1);
                s += __shfl_xor_sync(0xffffffffu, s, 2);
                if (tig == 0) rsumS[r * 4 + wn] = s;
            }
        __syncthreads();
        if (tid < 128) {
            int r = tid;
            float M = fmaxf(fmaxf(rmaxS[r * 4], rmaxS[r * 4 + 1]),
                            fmaxf(rmaxS[r * 4 + 2], rmaxS[r * 4 + 3]));
            float S = rsumS[r * 4] + rsumS[r * 4 + 1] + rsumS[r * 4 + 2] + rsumS[r * 4 + 3];
            long base = ((long)z * LTOK + row0 + r) * NCOLB + blockIdx.x;
            pmax[base] = M; psum[base] = S;
        }
    }
}

// ========== flash PV: fully cp.async NN GEMM with accumulator unit-rescaling ==========
// A-frags via ldmatrix; B (NN layout) keeps scalar LDS (transpose mapping unsupported).
__global__ void __launch_bounds__(256, 2)
mma_pv_flash(const float* __restrict__ P, const float* __restrict__ V,
             float* __restrict__ C,
             const float* __restrict__ rowmax, const float* __restrict__ rowinv,
             const float* __restrict__ pmax)
{
    extern __shared__ unsigned smem[];          // 2 * (A 4608 + B 4352) = 17920 words
    int z = blockIdx.z;
    const float* A = P + (long)z * LTOK * LTOK;
    const float* B = V + (long)z * EDIM;
    float* Cz = C + (long)z * EDIM;
    const int lda = LTOK, ldb = NB * EDIM, ldc = NB * EDIM;
    int row0 = blockIdx.y * 128, col0 = blockIdx.x * 128;
    int tid = threadIdx.x, lane = tid & 31, warp = tid >> 5;
    int wm = warp >> 2, wn = warp & 3;
    int gid = lane >> 2, tig = lane & 3;
    float acc[4][4][4] = {};
    int ra = tid >> 3, ka = (tid & 7) << 2;
    int kb = tid >> 5, nb = (tid & 31) << 2;

    unsigned smem_b = (unsigned)__cvta_generic_to_shared(smem);
    int a_row = (lane & 7) + ((lane >> 3) & 1) * 8;
    int a_col = (lane >> 4) * 4;

    long rowbase = (long)z * LTOK + row0;
    float curm[8];
    #pragma unroll
    for (int mt = 0; mt < 4; mt++)
        #pragma unroll
        for (int h = 0; h < 2; h++)
            curm[mt * 2 + h] = pmax[(rowbase + wm * 64 + mt * 16 + h * 8 + gid) * NCOLB];

    {
        unsigned* As = smem; unsigned* Bs = smem + 4608;
        #pragma unroll
        for (int i = 0; i < 4; i++) {
            int r = ra + 32 * i;
            cp16(&As[r * 36 + ka], &A[(long)(row0 + r) * lda + ka]);
            int k = kb + 8 * i;
            cp16(&Bs[k * 136 + nb], &B[(long)k * ldb + col0 + nb]);
        }
        CP_COMMIT();
    }

    int nbuf = 0;
    for (int kt = 0; kt < LTOK; kt += 32) {
        bool more = (kt + 32) < LTOK;
        if (more) {
            unsigned* As = smem + (nbuf ^ 1) * 8960;
            unsigned* Bs = As + 4608;
            #pragma unroll
            for (int i = 0; i < 4; i++) {
                int r = ra + 32 * i;
                cp16(&As[r * 36 + ka], &A[(long)(row0 + r) * lda + kt + 32 + ka]);
                int k = kb + 8 * i;
                cp16(&Bs[k * 136 + nb], &B[(long)(kt + 32 + k) * ldb + col0 + nb]);
            }
            CP_COMMIT();
            CP_WAIT1();
        } else {
            CP_WAIT0();
        }
        __syncthreads();

        if (kt > 0 && (kt & 127) == 0) {
            int blk = kt >> 7;
            #pragma unroll
            for (int mt = 0; mt < 4; mt++)
                #pragma unroll
                for (int h = 0; h < 2; h++) {
                    long rr = rowbase + wm * 64 + mt * 16 + h * 8 + gid;
                    float nm = pmax[rr * NCOLB + blk];
                    float ratio = __expf(curm[mt * 2 + h] - nm);
                    curm[mt * 2 + h] = nm;
                    #pragma unroll
                    for (int nt = 0; nt < 4; nt++) {
                        acc[mt][nt][2 * h]     *= ratio;
                        acc[mt][nt][2 * h + 1] *= ratio;
                    }
                }
        }

        unsigned baseA = smem_b + (nbuf * 8960) * 4;
        const unsigned* Bs = smem + nbuf * 8960 + 4608;
        #pragma unroll
        for (int ks = 0; ks < 4; ks++) {
            int k0 = ks * 8;
            unsigned a[4][4], b[4][2];
            #pragma unroll
            for (int mt = 0; mt < 4; mt++)
                ldsm_x4(a[mt][0], a[mt][1], a[mt][2], a[mt][3],
                        baseA + ((wm * 64 + mt * 16 + a_row) * 36 + k0 + a_col) * 4);
            #pragma unroll
            for (int nt = 0; nt < 4; nt++) {
                int c = wn * 32 + nt * 8 + gid;
                b[nt][0] = Bs[(k0 + tig) * 136 + c];
                b[nt][1] = Bs[(k0 + tig + 4) * 136 + c];
            }
            #pragma unroll
            for (int mt = 0; mt < 4; mt++)
                #pragma unroll
                for (int nt = 0; nt < 4; nt++)
                    asm volatile(
                        "mma.sync.aligned.m16n8k8.row.col.f32.tf32.tf32.f32 "
                        "{%0,%1,%2,%3}, {%4,%5,%6,%7}, {%8,%9}, {%0,%1,%2,%3};\n"
                        : "+f"(acc[mt][nt][0]), "+f"(acc[mt][nt][1]),
                          "+f"(acc[mt][nt][2]), "+f"(acc[mt][nt][3])
                        : "r"(a[mt][0]), "r"(a[mt][1]), "r"(a[mt][2]), "r"(a[mt][3]),
                          "r"(b[nt][0]), "r"(b[nt][1]));
        }
        __syncthreads();
        nbuf ^= 1;
    }

    #pragma unroll
    for (int mt = 0; mt < 4; mt++) {
        int r0l = wm * 64 + mt * 16 + gid, r1l = r0l + 8;
        long rr0 = rowbase + r0l, rr1 = rowbase + r1l;
        float fa = __expf(curm[mt * 2 + 0] - rowmax[rr0]) * rowinv[rr0];
        float fb = __expf(curm[mt * 2 + 1] - rowmax[rr1]) * rowinv[rr1];
        #pragma unroll
        for (int nt = 0; nt < 4; nt++) {
            int c0l = wn * 32 + nt * 8 + 2 * tig;
            float2 o0 = { acc[mt][nt][0] * fa, acc[mt][nt][1] * fa };
            float2 o1 = { acc[mt][nt][2] * fb, acc[mt][nt][3] * fb };
            *(float2*)&Cz[(long)(row0 + r0l) * ldc + col0 + c0l] = o0;
            *(float2*)&Cz[(long)(row0 + r1l) * ldc + col0 + c0l] = o1;
        }
    }
}

// merge 32 block-partials per row -> rowmax, 1/rowsum
__global__ void stats_finish_kernel(const float* __restrict__ pmax, const float* __restrict__ psum,
                                    float* __restrict__ rmax, float* __restrict__ rinv)
{
    int row = blockIdx.x * 4 + (threadIdx.x >> 5);
    int lane = threadIdx.x & 31;
    float M = pmax[(long)row * NCOLB + lane];
    float S = psum[(long)row * NCOLB + lane];
    #pragma unroll
    for (int o = 16; o; o >>= 1) {
        float M2 = __shfl_xor_sync(0xffffffffu, M, o);
        float S2 = __shfl_xor_sync(0xffffffffu, S, o);
        float Mn = fmaxf(M, M2);
        S = S * __expf(M - Mn) + S2 * __expf(M2 - Mn);
        M = Mn;
    }
    if (lane == 0) { rmax[row] = M; rinv[row] = 1.f / S; }
}

// ---------------- small row-GEMM: 4 independent accumulators ----------------
__global__ void small_gemm_kernel(const float* __restrict__ X, int K,
                                  const float* __restrict__ W,
                                  const float* __restrict__ bias,
                                  float* __restrict__ Out, int ldo,
                                  int mode, float scale)
{
    __shared__ float xs[DFFDIM];
    int r = blockIdx.x, tid = threadIdx.x;
    for (int i = tid; i < K; i += 128) xs[i] = X[(long)r * K + i];
    __syncthreads();
    int o = blockIdx.y * 128 + tid;
    const float4* w4 = (const float4*)(W + (long)o * K);
    const float4* x4 = (const float4*)xs;
    float a0 = 0.f, a1 = 0.f, a2 = 0.f, a3 = 0.f;
    int K4 = K >> 2;
    for (int k = 0; k < K4; k += 4) {
        float4 w0 = w4[k],     x0 = x4[k];
        float4 w1 = w4[k + 1], x1 = x4[k + 1];
        float4 w2 = w4[k + 2], x2 = x4[k + 2];
        float4 w3 = w4[k + 3], x3 = x4[k + 3];
        a0 += w0.x * x0.x + w0.y * x0.y + w0.z * x0.z + w0.w * x0.w;
        a1 += w1.x * x1.x + w1.y * x1.y + w1.z * x1.z + w1.w * x1.w;
        a2 += w2.x * x2.x + w2.y * x2.y + w2.z * x2.z + w2.w * x2.w;
        a3 += w3.x * x3.x + w3.y * x3.y + w3.z * x3.z + w3.w * x3.w;
    }
    float acc = (a0 + a1) + (a2 + a3);
    float v;
    if (mode == 0) v = acc * scale;
    else if (mode == 1) { float t = acc + bias[o]; v = 0.5f * t * (1.0f + erff(t * 0.70710678118654752f)); }
    else v = acc + bias[o];
    Out[(long)r * ldo + o] = v;
}

// ---------------- softmax rows of 4096 (slot attsm only) ----------------
__global__ void softmax_rows_kernel(const float* __restrict__ In, float* __restrict__ Out)
{
    __shared__ float buf[LTOK];
    __shared__ float red[256];
    long base = (long)blockIdx.x * LTOK;
    int tid = threadIdx.x;
    float mx = -3.4e38f;
    for (int i = tid; i < LTOK; i += 256) { float v = In[base + i]; buf[i] = v; mx = fmaxf(mx, v); }
    red[tid] = mx; __syncthreads();
    for (int st = 128; st > 0; st >>= 1) { if (tid < st) red[tid] = fmaxf(red[tid], red[tid + st]); __syncthreads(); }
    mx = red[0]; __syncthreads();
    float s = 0.f;
    for (int i = tid; i < LTOK; i += 256) { float e = expf(buf[i] - mx); buf[i] = e; s += e; }
    red[tid] = s; __syncthreads();
    for (int st = 128; st > 0; st >>= 1) { if (tid < st) red[tid] += red[tid + st]; __syncthreads(); }
    float inv = 1.f / red[0];
    for (int i = tid; i < LTOK; i += 256) Out[base + i] = buf[i] * inv;
}

// ---------------- slot-phase small kernels ----------------
__global__ void init_slots_kernel(const float* __restrict__ sv)
{
    int idx = blockIdx.x * 256 + threadIdx.x;
    if (idx < NB * MSLOT * EDIM) {
        int e = idx % EDIM; int nm = idx / EDIM; int m = nm % MSLOT; int n = nm / MSLOT;
        g_slots[idx] = sv[(m * NB + n) * EDIM + e];
    }
}

__global__ void slots_out_kernel(float* __restrict__ out)
{
    int idx = blockIdx.x * 256 + threadIdx.x;
    if (idx < NB * MSLOT * EDIM) {
        int e = idx % EDIM; int nm = idx / EDIM; int m = nm % MSLOT; int n = nm / MSLOT;
        out[(m * NB + n) * EDIM + e] = g_slots[idx];
    }
}

__global__ void slot_att_kernel()
{
    int n = blockIdx.x;
    int l = blockIdx.y * 128 + threadIdx.x;
    __shared__ float Qsm[MSLOT * EDIM];
    const float* src = g_Qs + n * MSLOT * EDIM;
    for (int i = threadIdx.x; i < MSLOT * EDIM; i += 128) Qsm[i] = src[i];
    __syncthreads();
    const float4* kr = (const float4*)(g_Kp + (long)(l * NB + n) * EDIM);
    float acc[MSLOT] = {};
    for (int e4 = 0; e4 < EDIM / 4; e4++) {
        float4 kv = kr[e4];
        #pragma unroll
        for (int m = 0; m < MSLOT; m++) {
            float4 q = *(const float4*)&Qsm[m * EDIM + e4 * 4];
            acc[m] += q.x * kv.x + q.y * kv.y + q.z * kv.z + q.w * kv.w;
        }
    }
    #pragma unroll
    for (int m = 0; m < MSLOT; m++) g_att[(long)(n * MSLOT + m) * LTOK + l] = acc[m];
}

__global__ void slot_assign_kernel(float* __restrict__ outp)
{
    int n = blockIdx.x;
    int l = blockIdx.y * 256 + threadIdx.x;
    float v[MSLOT]; float mx = -3.4e38f;
    #pragma unroll
    for (int m = 0; m < MSLOT; m++) { v[m] = g_att[(long)(n * MSLOT + m) * LTOK + l]; mx = fmaxf(mx, v[m]); }
    float s = 0.f;
    #pragma unroll
    for (int m = 0; m < MSLOT; m++) { v[m] = expf(v[m] - mx); s += v[m]; }
    float inv = 1.f / s;
    #pragma unroll
    for (int m = 0; m < MSLOT; m++) outp[(long)(n * MSLOT + m) * LTOK + l] = v[m] * inv;
}

__global__ void slot_update_kernel()
{
    int n = blockIdx.x;
    int e = blockIdx.y * 128 + threadIdx.x;
    int z = blockIdx.z;
    __shared__ float w[MSLOT][128];
    float acc[MSLOT] = {};
    for (int l0 = z * 512; l0 < z * 512 + 512; l0 += 128) {
        #pragma unroll
        for (int m = 0; m < MSLOT; m++)
            w[m][threadIdx.x] = g_attsm[(long)(n * MSLOT + m) * LTOK + l0 + threadIdx.x];
        __syncthreads();
        for (int lt = 0; lt < 128; lt++) {
            float v = g_Vp[(long)((l0 + lt) * NB + n) * EDIM + e];
            #pragma unroll
            for (int m = 0; m < MSLOT; m++) acc[m] += w[m][lt] * v;
        }
        __syncthreads();
    }
    #pragma unroll
    for (int m = 0; m < MSLOT; m++)
        g_srcPart[z][(n * MSLOT + m) * EDIM + e] = acc[m];
}

__global__ void ln1_kernel(const float* __restrict__ gg, const float* __restrict__ bb)
{
    int r = blockIdx.x, tid = threadIdx.x;
    __shared__ float xs[EDIM];
    __shared__ float red[256];
    for (int i = tid; i < EDIM; i += 256) {
        float v = g_slots[r * EDIM + i];
        #pragma unroll
        for (int zz = 0; zz < 8; zz++) v += g_srcPart[zz][r * EDIM + i];
        xs[i] = v;
    }
    __syncthreads();
    float s = 0.f;
    for (int i = tid; i < EDIM; i += 256) s += xs[i];
    red[tid] = s; __syncthreads();
    for (int st = 128; st > 0; st >>= 1) { if (tid < st) red[tid] += red[tid + st]; __syncthreads(); }
    float mean = red[0] / EDIM;
    __syncthreads();
    float sq = 0.f;
    for (int i = tid; i < EDIM; i += 256) { float d = xs[i] - mean; sq += d * d; }
    red[tid] = sq; __syncthreads();
    for (int st = 128; st > 0; st >>= 1) { if (tid < st) red[tid] += red[tid + st]; __syncthreads(); }
    float rstd = rsqrtf(red[0] / EDIM + LNEPS);
    for (int i = tid; i < EDIM; i += 256)
        g_srcn[r * EDIM + i] = (xs[i] - mean) * rstd * gg[i] + bb[i];
}

__global__ void ln2_kernel(const float* __restrict__ gg, const float* __restrict__ bb)
{
    int r = blockIdx.x, tid = threadIdx.x;
    __shared__ float xs[EDIM];
    __shared__ float red[256];
    for (int i = tid; i < EDIM; i += 256)
        xs[i] = g_srcn[r * EDIM + i] + g_f2[r * EDIM + i];
    __syncthreads();
    float s = 0.f;
    for (int i = tid; i < EDIM; i += 256) s += xs[i];
    red[tid] = s; __syncthreads();
    for (int st = 128; st > 0; st >>= 1) { if (tid < st) red[tid] += red[tid + st]; __syncthreads(); }
    float mean = red[0] / EDIM;
    __syncthreads();
    float sq = 0.f;
    for (int i = tid; i < EDIM; i += 256) { float d = xs[i] - mean; sq += d * d; }
    red[tid] = sq; __syncthreads();
    for (int st = 128; st > 0; st >>= 1) { if (tid < st) red[tid] += red[tid + st]; __syncthreads(); }
    float rstd = rsqrtf(red[0] / EDIM + LNEPS);
    for (int i = tid; i < EDIM; i += 256)
        g_slots[r * EDIM + i] = (xs[i] - mean) * rstd * gg[i] + bb[i];
}

__global__ void slot_att_final_kernel(const float* __restrict__ Qf, float* __restrict__ outp)
{
    int n = blockIdx.x;
    int l = blockIdx.y * 128 + threadIdx.x;
    __shared__ float S[MSLOT * EDIM];
    const float* sp = g_slots + n * MSLOT * EDIM;
    for (int i = threadIdx.x; i < MSLOT * EDIM; i += 128) S[i] = sp[i];
    __syncthreads();
    const float4* q4 = (const float4*)(Qf + (long)(l * NB + n) * EDIM);
    float acc[MSLOT] = {};
    for (int e4 = 0; e4 < EDIM / 4; e4++) {
        float4 q = q4[e4];
        #pragma unroll
        for (int m = 0; m < MSLOT; m++) {
            float4 sv = *(const float4*)&S[m * EDIM + e4 * 4];
            acc[m] += sv.x * q.x + sv.y * q.y + sv.z * q.z + sv.w * q.w;
        }
    }
    float mx = -3.4e38f;
    #pragma unroll
    for (int m = 0; m < MSLOT; m++) mx = fmaxf(mx, acc[m]);
    float s = 0.f;
    #pragma unroll
    for (int m = 0; m < MSLOT; m++) { acc[m] = expf(acc[m] - mx); s += acc[m]; }
    float inv = 1.f / s;
    #pragma unroll
    for (int m = 0; m < MSLOT; m++) outp[(long)(n * LTOK + l) * MSLOT + m] = acc[m] * inv;
}

// ---------------- host launcher ----------------
extern "C" void kernel_launch(void* const* d_in, const int* in_sizes, int n_in,
                              void* d_out, int out_size)
{
    const float* queries = (const float*)d_in[0];
    const float* keys    = (const float*)d_in[1];
    const float* values  = (const float*)d_in[2];
    const float* slot_v  = (const float*)d_in[3];
    const float* sWq = (const float*)d_in[4];
    const float* sWk = (const float*)d_in[5];
    const float* sWv = (const float*)d_in[6];
    const float* Wq  = (const float*)d_in[7];
    const float* Wk  = (const float*)d_in[8];
    const float* Wv  = (const float*)d_in[9];
    const float* l1_w = (const float*)d_in[10];
    const float* l1_b = (const float*)d_in[11];
    const float* l2_w = (const float*)d_in[12];
    const float* l2_b = (const float*)d_in[13];
    const float* n1_g = (const float*)d_in[14];
    const float* n1_b = (const float*)d_in[15];
    const float* n2_g = (const float*)d_in[16];
    const float* n2_b = (const float*)d_in[17];
    float* out = (float*)d_out;

    float *Kp, *Vp, *Vf, *VfR, *P, *Pmax, *Psum, *Rmax, *Rinv;
    float *slots, *Qs, *att, *attsm, *srcn, *hbuf, *f2;
    float *qR, *kR, *vR, *QfR, *KfR, *wR;
    cudaGetSymbolAddress((void**)&Kp,    g_Kp);
    cudaGetSymbolAddress((void**)&Vp,    g_Vp);
    cudaGetSymbolAddress((void**)&Vf,    g_Vf);
    cudaGetSymbolAddress((void**)&VfR,   g_VfR);
    cudaGetSymbolAddress((void**)&P,     g_P);
    cudaGetSymbolAddress((void**)&Pmax,  g_Pmax);
    cudaGetSymbolAddress((void**)&Psum,  g_Psum);
    cudaGetSymbolAddress((void**)&Rmax,  g_Rmax);
    cudaGetSymbolAddress((void**)&Rinv,  g_Rinv);
    cudaGetSymbolAddress((void**)&slots, g_slots);
    cudaGetSymbolAddress((void**)&Qs,    g_Qs);
    cudaGetSymbolAddress((void**)&att,   g_att);
    cudaGetSymbolAddress((void**)&attsm, g_attsm);
    cudaGetSymbolAddress((void**)&srcn,  g_srcn);
    cudaGetSymbolAddress((void**)&hbuf,  g_h);
    cudaGetSymbolAddress((void**)&f2,    g_f2);
    cudaGetSymbolAddress((void**)&qR,    g_qR);
    cudaGetSymbolAddress((void**)&kR,    g_kR);
    cudaGetSymbolAddress((void**)&vR,    g_vR);
    cudaGetSymbolAddress((void**)&QfR,   g_QfR);
    cudaGetSymbolAddress((void**)&KfR,   g_KfR);
    cudaGetSymbolAddress((void**)&wR,    g_wR);

    const int o_Q       = LTOK * NB * EDIM;
    const int o_K       = 2 * o_Q;
    const int o_slots   = 3 * o_Q;
    const int o_sassign = o_slots + MSLOT * NB * EDIM;
    const int o_satt    = o_sassign + NB * MSLOT * LTOK;

    const int SMEM_ASYNC = 2 * (4608 + 4608) * 4;   // 73728 B
    const int SMEM_PV    = 2 * (4608 + 4352) * 4;   // 71680 B
    cudaFuncSetAttribute(mma_async_kernel<0>, cudaFuncAttributeMaxDynamicSharedMemorySize, SMEM_ASYNC);
    cudaFuncSetAttribute(mma_async_kernel<1>, cudaFuncAttributeMaxDynamicSharedMemorySize, SMEM_ASYNC);
    cudaFuncSetAttribute(mma_pv_flash,        cudaFuncAttributeMaxDynamicSharedMemorySize, SMEM_PV);

    // ---- pre-round operands to tf32 (makes cp.async raw moves exact) ----
    const int NTOK4 = (NB * LTOK * EDIM) / 4;       // 2097152
    const int NW4   = (EDIM * EDIM) / 4;            // 65536
    round_tf32_kernel<<<(NTOK4 + 255) / 256, 256>>>(queries, qR, NTOK4);
    round_tf32_kernel<<<(NTOK4 + 255) / 256, 256>>>(keys,    kR, NTOK4);
    round_tf32_kernel<<<(NTOK4 + 255) / 256, 256>>>(values,  vR, NTOK4);
    round_tf32_kernel<<<(NW4 + 255) / 256, 256>>>(sWk, wR + 0L * EDIM * EDIM, NW4);
    round_tf32_kernel<<<(NW4 + 255) / 256, 256>>>(sWv, wR + 1L * EDIM * EDIM, NW4);
    round_tf32_kernel<<<(NW4 + 255) / 256, 256>>>(Wq,  wR + 2L * EDIM * EDIM, NW4);
    round_tf32_kernel<<<(NW4 + 255) / 256, 256>>>(Wk,  wR + 3L * EDIM * EDIM, NW4);
    round_tf32_kernel<<<(NW4 + 255) / 256, 256>>>(Wv,  wR + 4L * EDIM * EDIM, NW4);

    dim3 gProj(EDIM / 128, (LTOK * NB) / 128, 1);

    mma_async_kernel<0><<<gProj, 256, SMEM_ASYNC>>>(qR, EDIM, 0, wR + 0L * EDIM * EDIM, EDIM, 0,
                                                    Kp, EDIM, 0, 0, EDIM, 1.0f, 0, 0, 0, 0);
    mma_async_kernel<0><<<gProj, 256, SMEM_ASYNC>>>(qR, EDIM, 0, wR + 1L * EDIM * EDIM, EDIM, 0,
                                                    Vp, EDIM, 0, 0, EDIM, 1.0f, 0, 0, 0, 0);
    init_slots_kernel<<<96, 256>>>(slot_v);

    for (int c = 0; c < NCYC; c++) {
        small_gemm_kernel<<<dim3(NB * MSLOT, EDIM / 128), 128>>>(slots, EDIM, sWq, 0, Qs, EDIM, 0, SCALE_Q);
        slot_att_kernel<<<dim3(NB, LTOK / 128), 128>>>();
        softmax_rows_kernel<<<NB * MSLOT, 256>>>(att, attsm);
        if (c == NCYC - 1)
            slot_assign_kernel<<<dim3(NB, LTOK / 256), 256>>>(out + o_sassign);
        slot_update_kernel<<<dim3(NB, EDIM / 128, 8), 128>>>();
        ln1_kernel<<<NB * MSLOT, 256>>>(n1_g, n1_b);
        small_gemm_kernel<<<dim3(NB * MSLOT, DFFDIM / 128), 128>>>(srcn, EDIM, l1_w, l1_b, hbuf, DFFDIM, 1, 1.0f);
        small_gemm_kernel<<<dim3(NB * MSLOT, EDIM / 128), 128>>>(hbuf, DFFDIM, l2_w, l2_b, f2, EDIM, 2, 1.0f);
        ln2_kernel<<<NB * MSLOT, 256>>>(n2_g, n2_b);
    }

    slots_out_kernel<<<96, 256>>>(out + o_slots);

    // final projections (emit tf32-rounded copies of Q, K, V for exact cp.async)
    mma_async_kernel<0><<<gProj, 256, SMEM_ASYNC>>>(qR, EDIM, 0, wR + 2L * EDIM * EDIM, EDIM, 0,
                                                    out + o_Q, EDIM, 0, QfR, EDIM, SCALE_Q, 0, 0, 0, 0);
    mma_async_kernel<0><<<gProj, 256, SMEM_ASYNC>>>(kR, EDIM, 0, wR + 3L * EDIM * EDIM, EDIM, 0,
                                                    out + o_K, EDIM, 0, KfR, EDIM, 1.0f, 0, 0, 0, 0);
    mma_async_kernel<0><<<gProj, 256, SMEM_ASYNC>>>(vR, EDIM, 0, wR + 4L * EDIM * EDIM, EDIM, 0,
                                                    Vf, EDIM, 0, VfR, EDIM, 1.0f, 0, 0, 0, 0);

    slot_att_final_kernel<<<dim3(NB, LTOK / 128), 128>>>(out + o_Q, out + o_satt);

    // logits (gated) -> exp'd P + online-softmax block partials
    mma_async_kernel<1><<<dim3(NCOLB, LTOK / 128, NB), 256, SMEM_ASYNC>>>(
        QfR, NB * EDIM, EDIM,
        KfR, NB * EDIM, EDIM,
        P, LTOK, (long)LTOK * LTOK, 0,
        EDIM, 1.0f, out + o_satt, out + o_sassign, Pmax, Psum);
    stats_finish_kernel<<<NB * LTOK / 4, 128>>>(Pmax, Psum, Rmax, Rinv);
    // out = softmax(P) @ V  (flash-style, fully cp.async)
    mma_pv_flash<<<dim3(EDIM / 128, LTOK / 128, NB), 256, SMEM_PV>>>(
        P, VfR, out, Rmax, Rinv, Pmax);
}